// round 8
// baseline (speedup 1.0000x reference)
#include <cuda_runtime.h>
#include <cuda_fp16.h>
#include <cstdint>

// ============================================================
// out[8192,4096] = x[8192,4096] @ sign(W)[4096,4096]^T + sign(b)
// Base-PTX tensor path: cp.async + ldmatrix + mma.sync.m16n8k16.f32.f16.
// R8: block 128x256 (256 thr, 1 CTA/SM) -> 25% fewer LDGSTS per FLOP,
//     single barrier domain; mbarrier pipeline with cheap empty barriers
//     (count=8, one arrive per warp) fixing R7's arrival-traffic cost.
// ============================================================

static constexpr int M = 8192;
static constexpr int N = 4096;
static constexpr int K = 4096;

static constexpr int BM = 128;
static constexpr int BN = 256;
static constexpr int BK = 64;
static constexpr int KT = K / BK;          // 64 k-tiles
static constexpr int STAGES = 3;
static constexpr int NTHREADS = 256;

static constexpr int ROW_HALFS = BK + 8;   // 72 halves = 144B row (9x16B, conflict-free)
static constexpr int ROW_BYTES = ROW_HALFS * 2;              // 144
static constexpr int A_TILE_BYTES = BM * ROW_BYTES;          // 18432
static constexpr int B_TILE_BYTES = BN * ROW_BYTES;          // 36864
static constexpr int STAGE_BYTES = A_TILE_BYTES + B_TILE_BYTES; // 55296
static constexpr int SMEM_DATA = 1024;                       // barriers below
static constexpr int SMEM_TOTAL = SMEM_DATA + STAGES * STAGE_BYTES; // 166912

// ---------------- scratch (__device__ globals: alloc-free rule) ------------
__device__ __half g_xh[(size_t)M * K];   // fp16(x)
__device__ __half g_wh[(size_t)N * K];   // fp16(sign(W))
__device__ float  g_bs[N];               // sign(bias)

// ---------------- PTX helpers -----------------------------------------------
__device__ __forceinline__ uint32_t smem_u32(const void* p) {
    uint32_t a;
    asm("{ .reg .u64 t; cvta.to.shared.u64 t, %1; cvt.u32.u64 %0, t; }"
        : "=r"(a) : "l"(p));
    return a;
}

__device__ __forceinline__ void cp16(uint32_t s, const void* g) {
    asm volatile("cp.async.cg.shared.global [%0], [%1], 16;"
                 :: "r"(s), "l"(g) : "memory");
}

#define MBAR_INIT(a, c) \
    asm volatile("mbarrier.init.shared.b64 [%0], %1;" :: "r"(a), "r"((uint32_t)(c)) : "memory")
#define MBAR_ARRIVE(a) \
    asm volatile("mbarrier.arrive.shared.b64 _, [%0];" :: "r"(a) : "memory")
// arrive on mbarrier when all of this thread's prior cp.asyncs complete
#define CP_MBAR_ARRIVE(a) \
    asm volatile("cp.async.mbarrier.arrive.noinc.shared.b64 [%0];" :: "r"(a) : "memory")

#define MBAR_WAIT(a, ph) do {                                               \
    uint32_t _m = (a); uint32_t _p = (ph); uint32_t _d;                     \
    asm volatile("{ .reg .pred p;"                                          \
        " mbarrier.try_wait.parity.shared.b64 p, [%1], %2;"                 \
        " selp.b32 %0, 1, 0, p; }" : "=r"(_d) : "r"(_m), "r"(_p) : "memory");\
    if (!_d) {                                                              \
        asm volatile("{ .reg .pred P1;"                                     \
            " WL_%=: mbarrier.try_wait.parity.shared.b64 P1, [%0], %1, 0x989680;"\
            " @P1 bra.uni WD_%=; bra.uni WL_%=; WD_%=: }"                   \
            :: "r"(_m), "r"(_p) : "memory");                                \
    } } while (0)

__device__ __forceinline__ void ldsm4(uint32_t* r, uint32_t addr) {
    asm volatile("ldmatrix.sync.aligned.m8n8.x4.shared.b16 {%0,%1,%2,%3}, [%4];"
                 : "=r"(r[0]), "=r"(r[1]), "=r"(r[2]), "=r"(r[3]) : "r"(addr));
}

__device__ __forceinline__ void mma16816(float* c, const uint32_t* a,
                                         uint32_t b0, uint32_t b1) {
    asm volatile(
        "mma.sync.aligned.m16n8k16.row.col.f32.f16.f16.f32 "
        "{%0,%1,%2,%3}, {%4,%5,%6,%7}, {%8,%9}, {%0,%1,%2,%3};"
        : "+f"(c[0]), "+f"(c[1]), "+f"(c[2]), "+f"(c[3])
        : "r"(a[0]), "r"(a[1]), "r"(a[2]), "r"(a[3]), "r"(b0), "r"(b1));
}

// ---------------- prep: fp32 -> fp16 / sign ---------------------------------
__device__ __forceinline__ float fsign(float v) {
    return (v > 0.f) ? 1.f : ((v < 0.f) ? -1.f : 0.f);
}

__global__ void prep_kernel(const float* __restrict__ x,
                            const float* __restrict__ w,
                            const float* __restrict__ b) {
    const long tid = (long)blockIdx.x * blockDim.x + threadIdx.x;
    const long stride = (long)gridDim.x * blockDim.x;
    const long NX4 = ((long)M * K) / 4;
    const long NW4 = ((long)N * K) / 4;

    __half2* xh2 = reinterpret_cast<__half2*>(g_xh);
    __half2* wh2 = reinterpret_cast<__half2*>(g_wh);

    for (long t = tid; t < NX4; t += stride) {
        float4 v = reinterpret_cast<const float4*>(x)[t];
        xh2[2 * t + 0] = __floats2half2_rn(v.x, v.y);
        xh2[2 * t + 1] = __floats2half2_rn(v.z, v.w);
    }
    for (long t = tid; t < NW4; t += stride) {
        float4 v = reinterpret_cast<const float4*>(w)[t];
        wh2[2 * t + 0] = __floats2half2_rn(fsign(v.x), fsign(v.y));
        wh2[2 * t + 1] = __floats2half2_rn(fsign(v.z), fsign(v.w));
    }
    if (tid < N) g_bs[tid] = fsign(b[tid]);
}

// ---------------- GEMM -------------------------------------------------------
// grid (N/BN=16, M/BM=64), 256 threads (8 warps: 2m x 4n), warp tile 64x64.
// 3-stage pipeline; full[s]: cp.async HW arrivals (count 256);
// empty[s]: one arrive per warp (count 8).
__global__ void __launch_bounds__(NTHREADS, 1)
gemm_kernel(float* __restrict__ out) {
    extern __shared__ __half smem[];
    const uint32_t sbase = smem_u32(smem);

    const int tid = threadIdx.x;
    const int wid = tid >> 5;
    const int lane = tid & 31;
    const int warp_m = wid & 1;         // 0..1
    const int warp_n = wid >> 1;        // 0..3

    const int bn = blockIdx.x;          // 0..15
    const int bm = blockIdx.y;          // 0..63

    const __half* gA = g_xh + (size_t)(bm * BM) * K;
    const __half* gB = g_wh + (size_t)(bn * BN) * K;

    auto full_bar  = [&](int s) { return sbase + (uint32_t)s * 16; };
    auto empty_bar = [&](int s) { return sbase + (uint32_t)s * 16 + 8; };

    // ldmatrix per-lane bases
    const int rowA = warp_m * 64 + (lane & 15);
    const int kbA  = (lane >> 4) * 8;                        // halves
    const int rowB = warp_n * 64 + (lane & 7) + (lane >> 4) * 8;
    const int kbB  = ((lane >> 3) & 1) * 8;                  // halves

    float acc[4][8][4];
    #pragma unroll
    for (int i = 0; i < 4; i++)
        #pragma unroll
        for (int j = 0; j < 8; j++)
            #pragma unroll
            for (int e = 0; e < 4; e++) acc[i][j][e] = 0.f;

    auto issue_stage = [&](int kt) {
        const int st = kt % STAGES;
        const uint32_t sA = sbase + SMEM_DATA + st * STAGE_BYTES;
        const uint32_t sB = sA + A_TILE_BYTES;
        // A: 1024 16B-chunks (128 rows x 8)
        #pragma unroll
        for (int i = 0; i < 4; i++) {
            const int c = tid + i * NTHREADS;
            const int row = c >> 3;
            const int kc = c & 7;
            cp16(sA + row * ROW_BYTES + kc * 16,
                 gA + (size_t)row * K + (size_t)kt * BK + kc * 8);
        }
        // B: 2048 16B-chunks (256 rows x 8)
        #pragma unroll
        for (int i = 0; i < 8; i++) {
            const int c = tid + i * NTHREADS;
            const int row = c >> 3;
            const int kc = c & 7;
            cp16(sB + row * ROW_BYTES + kc * 16,
                 gB + (size_t)row * K + (size_t)kt * BK + kc * 8);
        }
        CP_MBAR_ARRIVE(full_bar(st));    // HW arrival when this thread's cps land
    };

    auto load_frags = [&](int stage, int kk, uint32_t (*a)[4], uint32_t (*b)[4]) {
        const uint32_t sA = sbase + SMEM_DATA + stage * STAGE_BYTES;
        const uint32_t sB = sA + A_TILE_BYTES;
        #pragma unroll
        for (int im = 0; im < 4; im++)
            ldsm4(a[im], sA + (rowA + im * 16) * ROW_BYTES + (kbA + kk * 16) * 2);
        #pragma unroll
        for (int q = 0; q < 4; q++)
            ldsm4(b[q], sB + (rowB + q * 16) * ROW_BYTES + (kbB + kk * 16) * 2);
    };

    auto mma_half = [&](uint32_t (*a)[4], uint32_t (*b)[4]) {
        #pragma unroll
        for (int im = 0; im < 4; im++)
            #pragma unroll
            for (int jn = 0; jn < 8; jn++)
                mma16816(acc[im][jn],
                         a[im], b[jn >> 1][(jn & 1) * 2],
                                b[jn >> 1][(jn & 1) * 2 + 1]);
    };

    // ---- init barriers: full count=256 (per-thread cp arrivals),
    //      empty count=8 (one per warp) ----
    if (tid == 0) {
        #pragma unroll
        for (int s = 0; s < STAGES; s++) {
            MBAR_INIT(full_bar(s), NTHREADS);
            MBAR_INIT(empty_bar(s), 8);
        }
    }
    __syncthreads();

    uint32_t a0[4][4], b0[4][4], a1[4][4], b1[4][4];

    // prologue: stages 0,1 in flight (buffers fresh, no empty wait)
    issue_stage(0);
    issue_stage(1);
    MBAR_WAIT(full_bar(0), 0);           // stage 0 resident (all threads' cps)
    load_frags(0, 0, a0, b0);

    for (int kt = 0; kt < KT; kt++) {
        const int s = kt % STAGES;

        load_frags(s, 1, a1, b1);

        // prefetch stage kt+2 into buffer (kt+2)%3 (stage kt-1's buffer);
        // wait until all 8 warps signaled consumption of stage kt-1.
        if (kt + 2 < KT) {
            if (kt >= 1)
                MBAR_WAIT(empty_bar((kt + 2) % STAGES), ((kt - 1) / STAGES) & 1);
            issue_stage(kt + 2);
        }
        mma_half(a0, b0);                   // kk=0

        load_frags(s, 2, a0, b0);
        mma_half(a1, b1);                   // kk=1
        load_frags(s, 3, a1, b1);
        mma_half(a0, b0);                   // kk=2

        if (kt + 1 < KT) {
            MBAR_WAIT(full_bar((kt + 1) % STAGES), ((kt + 1) / STAGES) & 1);
            load_frags((kt + 1) % STAGES, 0, a0, b0);
        }
        mma_half(a1, b1);                   // kk=3 consumes stage kt's last frags

        // this warp is done reading stage kt (kk3 mma issued => ldsm complete)
        if (lane == 0) MBAR_ARRIVE(empty_bar(s));
    }

    // ---------------- epilogue: add sign(bias), store fp32 ------------------
    const int col0 = bn * BN + warp_n * 64 + 2 * (lane & 3);
    const int row0 = bm * BM + warp_m * 64 + (lane >> 2);
    #pragma unroll
    for (int jn = 0; jn < 8; jn++) {
        const int c = col0 + jn * 8;
        const float b0v = g_bs[c];
        const float b1v = g_bs[c + 1];
        #pragma unroll
        for (int im = 0; im < 4; im++) {
            const int r = row0 + im * 16;
            float2 v0 = make_float2(acc[im][jn][0] + b0v, acc[im][jn][1] + b1v);
            float2 v1 = make_float2(acc[im][jn][2] + b0v, acc[im][jn][3] + b1v);
            *reinterpret_cast<float2*>(out + (size_t)r * N + c) = v0;
            *reinterpret_cast<float2*>(out + (size_t)(r + 8) * N + c) = v1;
        }
    }
}

// ---------------- host launch ------------------------------------------------
extern "C" void kernel_launch(void* const* d_in, const int* in_sizes, int n_in,
                              void* d_out, int out_size) {
    const float* x = (const float*)d_in[0];
    const float* w = (const float*)d_in[1];
    const float* b = (const float*)d_in[2];
    float* out = (float*)d_out;

    cudaFuncSetAttribute(gemm_kernel, cudaFuncAttributeMaxDynamicSharedMemorySize,
                         SMEM_TOTAL);

    prep_kernel<<<1024, 256>>>(x, w, b);

    dim3 grid(N / BN, M / BM);   // (16, 64)
    gemm_kernel<<<grid, NTHREADS, SMEM_TOTAL>>>(out);
}

// round 9
// speedup vs baseline: 1.0399x; 1.0399x over previous
#include <cuda_runtime.h>
#include <cuda_fp16.h>
#include <cstdint>

// ============================================================
// out[8192,4096] = x[8192,4096] @ sign(W)[4096,4096]^T + sign(b)
// Base-PTX tensor path: cp.async + ldmatrix + mma.sync.m16n8k16.f32.f16.
// R9: R6 shape (128 thr, BK=64, 3 stages, 2 CTA/SM) + mbarrier pipeline
//     with CHEAP empty barriers (count=4, one lane0-arrive per warp) and
//     LDGSTS bursts split in two to avoid LSU collision with ldsm.
// ============================================================

static constexpr int M = 8192;
static constexpr int N = 4096;
static constexpr int K = 4096;

static constexpr int BM = 128;
static constexpr int BN = 128;
static constexpr int BK = 64;
static constexpr int KT = K / BK;          // 64 k-tiles
static constexpr int STAGES = 3;
static constexpr int NTHREADS = 128;

static constexpr int ROW_HALFS = BK + 8;   // 72 halves = 144B row (9x16B, conflict-free)
static constexpr int ROW_BYTES = ROW_HALFS * 2;              // 144
static constexpr int TILE_BYTES = BM * ROW_BYTES;            // 18432
static constexpr int STAGE_BYTES = 2 * TILE_BYTES;           // 36864 (A then B)
static constexpr int SMEM_DATA = 1024;                       // barriers below
static constexpr int SMEM_TOTAL = SMEM_DATA + STAGES * STAGE_BYTES; // 111616

// ---------------- scratch (__device__ globals: alloc-free rule) ------------
__device__ __half g_xh[(size_t)M * K];   // fp16(x)
__device__ __half g_wh[(size_t)N * K];   // fp16(sign(W))
__device__ float  g_bs[N];               // sign(bias)

// ---------------- PTX helpers -----------------------------------------------
__device__ __forceinline__ uint32_t smem_u32(const void* p) {
    uint32_t a;
    asm("{ .reg .u64 t; cvta.to.shared.u64 t, %1; cvt.u32.u64 %0, t; }"
        : "=r"(a) : "l"(p));
    return a;
}

__device__ __forceinline__ void cp16(uint32_t s, const void* g) {
    asm volatile("cp.async.cg.shared.global [%0], [%1], 16;"
                 :: "r"(s), "l"(g) : "memory");
}

#define MBAR_INIT(a, c) \
    asm volatile("mbarrier.init.shared.b64 [%0], %1;" :: "r"(a), "r"((uint32_t)(c)) : "memory")
#define MBAR_ARRIVE(a) \
    asm volatile("mbarrier.arrive.shared.b64 _, [%0];" :: "r"(a) : "memory")
// arrive on mbarrier when all of this thread's prior cp.asyncs complete
#define CP_MBAR_ARRIVE(a) \
    asm volatile("cp.async.mbarrier.arrive.noinc.shared.b64 [%0];" :: "r"(a) : "memory")

#define MBAR_WAIT(a, ph) do {                                               \
    uint32_t _m = (a); uint32_t _p = (ph); uint32_t _d;                     \
    asm volatile("{ .reg .pred p;"                                          \
        " mbarrier.try_wait.parity.shared.b64 p, [%1], %2;"                 \
        " selp.b32 %0, 1, 0, p; }" : "=r"(_d) : "r"(_m), "r"(_p) : "memory");\
    if (!_d) {                                                              \
        asm volatile("{ .reg .pred P1;"                                     \
            " WL_%=: mbarrier.try_wait.parity.shared.b64 P1, [%0], %1, 0x989680;"\
            " @P1 bra.uni WD_%=; bra.uni WL_%=; WD_%=: }"                   \
            :: "r"(_m), "r"(_p) : "memory");                                \
    } } while (0)

__device__ __forceinline__ void ldsm4(uint32_t* r, uint32_t addr) {
    asm volatile("ldmatrix.sync.aligned.m8n8.x4.shared.b16 {%0,%1,%2,%3}, [%4];"
                 : "=r"(r[0]), "=r"(r[1]), "=r"(r[2]), "=r"(r[3]) : "r"(addr));
}

__device__ __forceinline__ void mma16816(float* c, const uint32_t* a,
                                         uint32_t b0, uint32_t b1) {
    asm volatile(
        "mma.sync.aligned.m16n8k16.row.col.f32.f16.f16.f32 "
        "{%0,%1,%2,%3}, {%4,%5,%6,%7}, {%8,%9}, {%0,%1,%2,%3};"
        : "+f"(c[0]), "+f"(c[1]), "+f"(c[2]), "+f"(c[3])
        : "r"(a[0]), "r"(a[1]), "r"(a[2]), "r"(a[3]), "r"(b0), "r"(b1));
}

// ---------------- prep: fp32 -> fp16 / sign ---------------------------------
__device__ __forceinline__ float fsign(float v) {
    return (v > 0.f) ? 1.f : ((v < 0.f) ? -1.f : 0.f);
}

__global__ void prep_kernel(const float* __restrict__ x,
                            const float* __restrict__ w,
                            const float* __restrict__ b) {
    const long tid = (long)blockIdx.x * blockDim.x + threadIdx.x;
    const long stride = (long)gridDim.x * blockDim.x;
    const long NX4 = ((long)M * K) / 4;
    const long NW4 = ((long)N * K) / 4;

    __half2* xh2 = reinterpret_cast<__half2*>(g_xh);
    __half2* wh2 = reinterpret_cast<__half2*>(g_wh);

    for (long t = tid; t < NX4; t += stride) {
        float4 v = reinterpret_cast<const float4*>(x)[t];
        xh2[2 * t + 0] = __floats2half2_rn(v.x, v.y);
        xh2[2 * t + 1] = __floats2half2_rn(v.z, v.w);
    }
    for (long t = tid; t < NW4; t += stride) {
        float4 v = reinterpret_cast<const float4*>(w)[t];
        wh2[2 * t + 0] = __floats2half2_rn(fsign(v.x), fsign(v.y));
        wh2[2 * t + 1] = __floats2half2_rn(fsign(v.z), fsign(v.w));
    }
    if (tid < N) g_bs[tid] = fsign(b[tid]);
}

// ---------------- GEMM -------------------------------------------------------
// grid (N/BN=32, M/BM=64), 128 threads (4 warps: 2m x 2n), warp tile 64x64.
// 3-stage pipeline: full[s] = cp.async HW arrivals (count 128);
// empty[s] = per-warp arrivals (count 4). LDGSTS split into two bursts.
__global__ void __launch_bounds__(NTHREADS, 2)
gemm_kernel(float* __restrict__ out) {
    extern __shared__ __half smem[];
    const uint32_t sbase = smem_u32(smem);

    const int tid = threadIdx.x;
    const int wid = tid >> 5;
    const int lane = tid & 31;
    const int warp_m = wid & 1;         // 0..1
    const int warp_n = wid >> 1;        // 0..1

    const int bn = blockIdx.x;          // 0..31
    const int bm = blockIdx.y;          // 0..63

    const __half* gA = g_xh + (size_t)(bm * BM) * K;
    const __half* gB = g_wh + (size_t)(bn * BN) * K;

    auto full_bar  = [&](int s) { return sbase + (uint32_t)s * 16; };
    auto empty_bar = [&](int s) { return sbase + (uint32_t)s * 16 + 8; };

    // ldmatrix per-lane bases
    const int rowA = warp_m * 64 + (lane & 15);
    const int kbA  = (lane >> 4) * 8;                        // halves
    const int rowB = warp_n * 64 + (lane & 7) + (lane >> 4) * 8;
    const int kbB  = ((lane >> 3) & 1) * 8;                  // halves

    float acc[4][8][4];
    #pragma unroll
    for (int i = 0; i < 4; i++)
        #pragma unroll
        for (int j = 0; j < 8; j++)
            #pragma unroll
            for (int e = 0; e < 4; e++) acc[i][j][e] = 0.f;

    // A-half of a stage: 8 cp16 per thread
    auto issue_A = [&](int kt) {
        const int st = kt % STAGES;
        const uint32_t sA = sbase + SMEM_DATA + st * STAGE_BYTES;
        #pragma unroll
        for (int i = 0; i < 8; i++) {
            const int c = tid + i * NTHREADS;
            const int row = c >> 3;
            const int kc = c & 7;
            cp16(sA + row * ROW_BYTES + kc * 16,
                 gA + (size_t)row * K + (size_t)kt * BK + kc * 8);
        }
    };
    // B-half + HW arrival (covers both halves: arrive observes all prior cps)
    auto issue_B = [&](int kt) {
        const int st = kt % STAGES;
        const uint32_t sB = sbase + SMEM_DATA + st * STAGE_BYTES + TILE_BYTES;
        #pragma unroll
        for (int i = 0; i < 8; i++) {
            const int c = tid + i * NTHREADS;
            const int row = c >> 3;
            const int kc = c & 7;
            cp16(sB + row * ROW_BYTES + kc * 16,
                 gB + (size_t)row * K + (size_t)kt * BK + kc * 8);
        }
        CP_MBAR_ARRIVE(full_bar(st));
    };

    auto load_frags = [&](int stage, int kk, uint32_t (*a)[4], uint32_t (*b)[4]) {
        const uint32_t sA = sbase + SMEM_DATA + stage * STAGE_BYTES;
        const uint32_t sB = sA + TILE_BYTES;
        #pragma unroll
        for (int im = 0; im < 4; im++)
            ldsm4(a[im], sA + (rowA + im * 16) * ROW_BYTES + (kbA + kk * 16) * 2);
        #pragma unroll
        for (int q = 0; q < 4; q++)
            ldsm4(b[q], sB + (rowB + q * 16) * ROW_BYTES + (kbB + kk * 16) * 2);
    };

    auto mma_half = [&](uint32_t (*a)[4], uint32_t (*b)[4]) {
        #pragma unroll
        for (int im = 0; im < 4; im++)
            #pragma unroll
            for (int jn = 0; jn < 8; jn++)
                mma16816(acc[im][jn],
                         a[im], b[jn >> 1][(jn & 1) * 2],
                                b[jn >> 1][(jn & 1) * 2 + 1]);
    };

    // ---- init: full count=128 (per-thread cp arrivals), empty count=4 ----
    if (tid == 0) {
        #pragma unroll
        for (int s = 0; s < STAGES; s++) {
            MBAR_INIT(full_bar(s), NTHREADS);
            MBAR_INIT(empty_bar(s), 4);
        }
    }
    __syncthreads();

    uint32_t a0[4][4], b0[4][4], a1[4][4], b1[4][4];

    // prologue: stages 0,1 in flight (fresh buffers, no empty wait)
    issue_A(0); issue_B(0);
    issue_A(1); issue_B(1);
    MBAR_WAIT(full_bar(0), 0);           // stage 0 resident (all threads' cps)
    load_frags(0, 0, a0, b0);

    for (int kt = 0; kt < KT; kt++) {
        const int s = kt % STAGES;
        const bool pf = (kt + 2 < KT);

        load_frags(s, 1, a1, b1);

        // license buffer (kt+2)%3 == (kt-1)%3: all 4 warps done reading kt-1
        if (pf) {
            if (kt >= 1)
                MBAR_WAIT(empty_bar((kt + 2) % STAGES), ((kt - 1) / STAGES) & 1);
            issue_A(kt + 2);             // first LDGSTS burst
        }
        mma_half(a0, b0);                   // kk=0

        load_frags(s, 2, a0, b0);
        if (pf) issue_B(kt + 2);         // second burst + HW arrival
        mma_half(a1, b1);                   // kk=1

        load_frags(s, 3, a1, b1);
        mma_half(a0, b0);                   // kk=2

        if (kt + 1 < KT) {
            MBAR_WAIT(full_bar((kt + 1) % STAGES), ((kt + 1) / STAGES) & 1);
            load_frags((kt + 1) % STAGES, 0, a0, b0);
        }
        mma_half(a1, b1);                   // kk=3 consumes stage kt's last frags

        // this warp done reading stage kt (kk3 mma consumed the registers)
        if (lane == 0) MBAR_ARRIVE(empty_bar(s));
    }

    // ---------------- epilogue: add sign(bias), store fp32 ------------------
    const int col0 = bn * BN + warp_n * 64 + 2 * (lane & 3);
    const int row0 = bm * BM + warp_m * 64 + (lane >> 2);
    #pragma unroll
    for (int jn = 0; jn < 8; jn++) {
        const int c = col0 + jn * 8;
        const float b0v = g_bs[c];
        const float b1v = g_bs[c + 1];
        #pragma unroll
        for (int im = 0; im < 4; im++) {
            const int r = row0 + im * 16;
            float2 v0 = make_float2(acc[im][jn][0] + b0v, acc[im][jn][1] + b1v);
            float2 v1 = make_float2(acc[im][jn][2] + b0v, acc[im][jn][3] + b1v);
            *reinterpret_cast<float2*>(out + (size_t)r * N + c) = v0;
            *reinterpret_cast<float2*>(out + (size_t)(r + 8) * N + c) = v1;
        }
    }
}

// ---------------- host launch ------------------------------------------------
extern "C" void kernel_launch(void* const* d_in, const int* in_sizes, int n_in,
                              void* d_out, int out_size) {
    const float* x = (const float*)d_in[0];
    const float* w = (const float*)d_in[1];
    const float* b = (const float*)d_in[2];
    float* out = (float*)d_out;

    cudaFuncSetAttribute(gemm_kernel, cudaFuncAttributeMaxDynamicSharedMemorySize,
                         SMEM_TOTAL);

    prep_kernel<<<1024, 256>>>(x, w, b);

    dim3 grid(N / BN, M / BM);   // (32, 64)
    gemm_kernel<<<grid, NTHREADS, SMEM_TOTAL>>>(out);
}

// round 10
// speedup vs baseline: 1.0698x; 1.0287x over previous
#include <cuda_runtime.h>
#include <cuda_fp16.h>
#include <cstdint>

// ============================================================
// out[8192,4096] = x[8192,4096] @ sign(W)[4096,4096]^T + sign(b)
// Base-PTX tensor path: cp.async + ldmatrix + mma.sync.m16n8k16.f32.f16.
// R10: R6 (best: BAR sync, BK=64, 3 stages, 2 CTA/SM) +
//   (a) phase-staggered k-loop per CTA to decorrelate co-resident CTAs'
//       barrier/LDGSTS bursts (one CTA covers the other's sync window);
//   (b) strength-reduced cp.async address math (pointer bump per stage).
// ============================================================

static constexpr int M = 8192;
static constexpr int N = 4096;
static constexpr int K = 4096;

static constexpr int BM = 128;
static constexpr int BN = 128;
static constexpr int BK = 64;
static constexpr int KT = K / BK;          // 64 k-tiles
static constexpr int STAGES = 3;
static constexpr int NTHREADS = 128;

static constexpr int ROW_HALFS = BK + 8;   // 72 halves = 144B row (9x16B, conflict-free)
static constexpr int ROW_BYTES = ROW_HALFS * 2;              // 144
static constexpr int TILE_BYTES = BM * ROW_BYTES;            // 18432
static constexpr int STAGE_BYTES = 2 * TILE_BYTES;           // 36864 (A then B)
static constexpr int SMEM_TOTAL = STAGES * STAGE_BYTES;      // 110592

// ---------------- scratch (__device__ globals: alloc-free rule) ------------
__device__ __half g_xh[(size_t)M * K];   // fp16(x)
__device__ __half g_wh[(size_t)N * K];   // fp16(sign(W))
__device__ float  g_bs[N];               // sign(bias)

// ---------------- PTX helpers -----------------------------------------------
__device__ __forceinline__ uint32_t smem_u32(const void* p) {
    uint32_t a;
    asm("{ .reg .u64 t; cvta.to.shared.u64 t, %1; cvt.u32.u64 %0, t; }"
        : "=r"(a) : "l"(p));
    return a;
}

__device__ __forceinline__ void cp16(uint32_t s, const void* g) {
    asm volatile("cp.async.cg.shared.global [%0], [%1], 16;"
                 :: "r"(s), "l"(g) : "memory");
}
__device__ __forceinline__ void cp_commit() {
    asm volatile("cp.async.commit_group;" ::: "memory");
}
template <int NN>
__device__ __forceinline__ void cp_wait() {
    asm volatile("cp.async.wait_group %0;" :: "n"(NN) : "memory");
}

__device__ __forceinline__ void ldsm4(uint32_t* r, uint32_t addr) {
    asm volatile("ldmatrix.sync.aligned.m8n8.x4.shared.b16 {%0,%1,%2,%3}, [%4];"
                 : "=r"(r[0]), "=r"(r[1]), "=r"(r[2]), "=r"(r[3]) : "r"(addr));
}

__device__ __forceinline__ void mma16816(float* c, const uint32_t* a,
                                         uint32_t b0, uint32_t b1) {
    asm volatile(
        "mma.sync.aligned.m16n8k16.row.col.f32.f16.f16.f32 "
        "{%0,%1,%2,%3}, {%4,%5,%6,%7}, {%8,%9}, {%0,%1,%2,%3};"
        : "+f"(c[0]), "+f"(c[1]), "+f"(c[2]), "+f"(c[3])
        : "r"(a[0]), "r"(a[1]), "r"(a[2]), "r"(a[3]), "r"(b0), "r"(b1));
}

// ---------------- prep: fp32 -> fp16 / sign ---------------------------------
__device__ __forceinline__ float fsign(float v) {
    return (v > 0.f) ? 1.f : ((v < 0.f) ? -1.f : 0.f);
}

__global__ void prep_kernel(const float* __restrict__ x,
                            const float* __restrict__ w,
                            const float* __restrict__ b) {
    const long tid = (long)blockIdx.x * blockDim.x + threadIdx.x;
    const long stride = (long)gridDim.x * blockDim.x;
    const long NX4 = ((long)M * K) / 4;
    const long NW4 = ((long)N * K) / 4;

    __half2* xh2 = reinterpret_cast<__half2*>(g_xh);
    __half2* wh2 = reinterpret_cast<__half2*>(g_wh);

    for (long t = tid; t < NX4; t += stride) {
        float4 v = reinterpret_cast<const float4*>(x)[t];
        xh2[2 * t + 0] = __floats2half2_rn(v.x, v.y);
        xh2[2 * t + 1] = __floats2half2_rn(v.z, v.w);
    }
    for (long t = tid; t < NW4; t += stride) {
        float4 v = reinterpret_cast<const float4*>(w)[t];
        wh2[2 * t + 0] = __floats2half2_rn(fsign(v.x), fsign(v.y));
        wh2[2 * t + 1] = __floats2half2_rn(fsign(v.z), fsign(v.w));
    }
    if (tid < N) g_bs[tid] = fsign(b[tid]);
}

// ---------------- GEMM -------------------------------------------------------
// grid (N/BN=32, M/BM=64), 128 threads (4 warps: 2m x 2n), warp tile 64x64.
// 3-stage cp.async pipeline (BK=64) + double-buffered register fragments.
// k-loop starts at a per-CTA phase offset (mod KT) to decorrelate the two
// co-resident CTAs on each SM.
__global__ void __launch_bounds__(NTHREADS, 2)
gemm_kernel(float* __restrict__ out) {
    extern __shared__ __half smem[];
    const uint32_t sbase = smem_u32(smem);

    const int tid = threadIdx.x;
    const int wid = tid >> 5;
    const int lane = tid & 31;
    const int warp_m = wid & 1;         // 0..1
    const int warp_n = wid >> 1;        // 0..1

    const int bn = blockIdx.x;          // 0..31
    const int bm = blockIdx.y;          // 0..63
    const int bid = bm * gridDim.x + bn;
    const int phase = (bid & 3) * (KT / 4);   // stagger co-resident CTAs

    // per-thread cp.async source pointers (advanced by BK halves per stage)
    const int ld_row = tid >> 3;              // 0..15
    const int ld_kc  = tid & 7;               // 0..7 (16B chunk within row)
    const __half* gA_t = g_xh + (size_t)(bm * BM + ld_row) * K + ld_kc * 8;
    const __half* gB_t = g_wh + (size_t)(bn * BN + ld_row) * K + ld_kc * 8;
    const uint32_t s_off = ld_row * ROW_BYTES + ld_kc * 16;

    // ldmatrix per-lane bases
    const int rowA = warp_m * 64 + (lane & 15);
    const int kbA  = (lane >> 4) * 8;                        // halves
    const int rowB = warp_n * 64 + (lane & 7) + (lane >> 4) * 8;
    const int kbB  = ((lane >> 3) & 1) * 8;                  // halves

    float acc[4][8][4];
    #pragma unroll
    for (int i = 0; i < 4; i++)
        #pragma unroll
        for (int j = 0; j < 8; j++)
            #pragma unroll
            for (int e = 0; e < 4; e++) acc[i][j][e] = 0.f;

    // issue stage for iteration j (kt = (j+phase)&(KT-1)), buffer j%3
    auto issue_stage = [&](int j) {
        const int kt = (j + phase) & (KT - 1);
        const uint32_t sA = sbase + (j % STAGES) * STAGE_BYTES + s_off;
        const uint32_t sB = sA + TILE_BYTES;
        const __half* gA = gA_t + (size_t)kt * BK;
        const __half* gB = gB_t + (size_t)kt * BK;
        #pragma unroll
        for (int r = 0; r < 8; r++) {   // 8 row-groups of 16 rows
            cp16(sA + r * (16 * ROW_BYTES), gA + (size_t)(r * 16) * K);
            cp16(sB + r * (16 * ROW_BYTES), gB + (size_t)(r * 16) * K);
        }
        cp_commit();
    };

    auto load_frags = [&](int stage, int kk, uint32_t (*a)[4], uint32_t (*b)[4]) {
        const uint32_t sA = sbase + stage * STAGE_BYTES;
        const uint32_t sB = sA + TILE_BYTES;
        #pragma unroll
        for (int im = 0; im < 4; im++)
            ldsm4(a[im], sA + (rowA + im * 16) * ROW_BYTES + (kbA + kk * 16) * 2);
        #pragma unroll
        for (int q = 0; q < 4; q++)
            ldsm4(b[q], sB + (rowB + q * 16) * ROW_BYTES + (kbB + kk * 16) * 2);
    };

    auto mma_half = [&](uint32_t (*a)[4], uint32_t (*b)[4]) {
        #pragma unroll
        for (int im = 0; im < 4; im++)
            #pragma unroll
            for (int jn = 0; jn < 8; jn++)
                mma16816(acc[im][jn],
                         a[im], b[jn >> 1][(jn & 1) * 2],
                                b[jn >> 1][(jn & 1) * 2 + 1]);
    };

    uint32_t a0[4][4], b0[4][4], a1[4][4], b1[4][4];

    // prologue: fill 2 stages; pending={0,1}, wait<=1 -> stage 0 resident
    issue_stage(0);
    issue_stage(1);
    cp_wait<1>();
    __syncthreads();
    load_frags(0, 0, a0, b0);

    for (int j = 0; j < KT; j++) {
        const int st  = j % STAGES;
        const int stn = (j + 1 < KT ? j + 1 : j) % STAGES;

        load_frags(st, 1, a1, b1);
        // Issue stage j+2 now (buffer (j-1)%3, consumed by all threads before
        // the barrier at the end of iteration j-1). Keeps pending={j+1, j+2}
        // at the cp_wait below, so wait<=1 proves stage j+1 resident.
        if (j + 2 < KT) issue_stage(j + 2);
        else cp_commit();               // keep group accounting uniform
        mma_half(a0, b0);                   // kk=0

        load_frags(st, 2, a0, b0);
        mma_half(a1, b1);                   // kk=1
        load_frags(st, 3, a1, b1);
        mma_half(a0, b0);                   // kk=2

        // stage j+1 landed (pending <=1) + visible to all threads; barrier
        // also licenses overwriting buffer (j)%3 by the issue in iter j+1.
        cp_wait<1>();
        __syncthreads();

        load_frags(stn, 0, a0, b0);         // next iteration, kk=0
        mma_half(a1, b1);                   // kk=3
    }

    // ---------------- epilogue: add sign(bias), store fp32 ------------------
    const int col0 = bn * BN + warp_n * 64 + 2 * (lane & 3);
    const int row0 = bm * BM + warp_m * 64 + (lane >> 2);
    #pragma unroll
    for (int jn = 0; jn < 8; jn++) {
        const int c = col0 + jn * 8;
        const float b0v = g_bs[c];
        const float b1v = g_bs[c + 1];
        #pragma unroll
        for (int im = 0; im < 4; im++) {
            const int r = row0 + im * 16;
            float2 v0 = make_float2(acc[im][jn][0] + b0v, acc[im][jn][1] + b1v);
            float2 v1 = make_float2(acc[im][jn][2] + b0v, acc[im][jn][3] + b1v);
            *reinterpret_cast<float2*>(out + (size_t)r * N + c) = v0;
            *reinterpret_cast<float2*>(out + (size_t)(r + 8) * N + c) = v1;
        }
    }
}

// ---------------- host launch ------------------------------------------------
extern "C" void kernel_launch(void* const* d_in, const int* in_sizes, int n_in,
                              void* d_out, int out_size) {
    const float* x = (const float*)d_in[0];
    const float* w = (const float*)d_in[1];
    const float* b = (const float*)d_in[2];
    float* out = (float*)d_out;

    cudaFuncSetAttribute(gemm_kernel, cudaFuncAttributeMaxDynamicSharedMemorySize,
                         SMEM_TOTAL);

    prep_kernel<<<1024, 256>>>(x, w, b);

    dim3 grid(N / BN, M / BM);   // (32, 64)
    gemm_kernel<<<grid, NTHREADS, SMEM_TOTAL>>>(out);
}

// round 11
// speedup vs baseline: 1.1088x; 1.0364x over previous
#include <cuda_runtime.h>
#include <cuda_fp16.h>
#include <cstdint>

// ============================================================
// out[8192,4096] = x[8192,4096] @ sign(W)[4096,4096]^T + sign(b)
// Base-PTX tensor path: cp.async + ldmatrix + mma.sync.m16n8k16.f32.f16.
// R11: R10 skeleton (BAR sync, BK=64, 3 stages, 2 CTA/SM) +
//   (a) LDGSTS spread: stage issue split into 4 quarter-groups, one per
//       kk-half (cp_wait<4> proves stage j+1 resident);
//   (b) anti-phase: odd co-resident CTA (bid/148 parity) sleeps ~500cyc
//       at start so the pair's barrier windows interleave.
// ============================================================

static constexpr int M = 8192;
static constexpr int N = 4096;
static constexpr int K = 4096;

static constexpr int BM = 128;
static constexpr int BN = 128;
static constexpr int BK = 64;
static constexpr int KT = K / BK;          // 64 k-tiles
static constexpr int STAGES = 3;
static constexpr int NTHREADS = 128;

static constexpr int ROW_HALFS = BK + 8;   // 72 halves = 144B row (9x16B, conflict-free)
static constexpr int ROW_BYTES = ROW_HALFS * 2;              // 144
static constexpr int TILE_BYTES = BM * ROW_BYTES;            // 18432
static constexpr int STAGE_BYTES = 2 * TILE_BYTES;           // 36864 (A then B)
static constexpr int SMEM_TOTAL = STAGES * STAGE_BYTES;      // 110592

// ---------------- scratch (__device__ globals: alloc-free rule) ------------
__device__ __half g_xh[(size_t)M * K];   // fp16(x)
__device__ __half g_wh[(size_t)N * K];   // fp16(sign(W))
__device__ float  g_bs[N];               // sign(bias)

// ---------------- PTX helpers -----------------------------------------------
__device__ __forceinline__ uint32_t smem_u32(const void* p) {
    uint32_t a;
    asm("{ .reg .u64 t; cvta.to.shared.u64 t, %1; cvt.u32.u64 %0, t; }"
        : "=r"(a) : "l"(p));
    return a;
}

__device__ __forceinline__ void cp16(uint32_t s, const void* g) {
    asm volatile("cp.async.cg.shared.global [%0], [%1], 16;"
                 :: "r"(s), "l"(g) : "memory");
}
__device__ __forceinline__ void cp_commit() {
    asm volatile("cp.async.commit_group;" ::: "memory");
}
template <int NN>
__device__ __forceinline__ void cp_wait() {
    asm volatile("cp.async.wait_group %0;" :: "n"(NN) : "memory");
}

__device__ __forceinline__ void ldsm4(uint32_t* r, uint32_t addr) {
    asm volatile("ldmatrix.sync.aligned.m8n8.x4.shared.b16 {%0,%1,%2,%3}, [%4];"
                 : "=r"(r[0]), "=r"(r[1]), "=r"(r[2]), "=r"(r[3]) : "r"(addr));
}

__device__ __forceinline__ void mma16816(float* c, const uint32_t* a,
                                         uint32_t b0, uint32_t b1) {
    asm volatile(
        "mma.sync.aligned.m16n8k16.row.col.f32.f16.f16.f32 "
        "{%0,%1,%2,%3}, {%4,%5,%6,%7}, {%8,%9}, {%0,%1,%2,%3};"
        : "+f"(c[0]), "+f"(c[1]), "+f"(c[2]), "+f"(c[3])
        : "r"(a[0]), "r"(a[1]), "r"(a[2]), "r"(a[3]), "r"(b0), "r"(b1));
}

// ---------------- prep: fp32 -> fp16 / sign ---------------------------------
__device__ __forceinline__ float fsign(float v) {
    return (v > 0.f) ? 1.f : ((v < 0.f) ? -1.f : 0.f);
}

__global__ void prep_kernel(const float* __restrict__ x,
                            const float* __restrict__ w,
                            const float* __restrict__ b) {
    const long tid = (long)blockIdx.x * blockDim.x + threadIdx.x;
    const long stride = (long)gridDim.x * blockDim.x;
    const long NX4 = ((long)M * K) / 4;
    const long NW4 = ((long)N * K) / 4;

    __half2* xh2 = reinterpret_cast<__half2*>(g_xh);
    __half2* wh2 = reinterpret_cast<__half2*>(g_wh);

    for (long t = tid; t < NX4; t += stride) {
        float4 v = reinterpret_cast<const float4*>(x)[t];
        xh2[2 * t + 0] = __floats2half2_rn(v.x, v.y);
        xh2[2 * t + 1] = __floats2half2_rn(v.z, v.w);
    }
    for (long t = tid; t < NW4; t += stride) {
        float4 v = reinterpret_cast<const float4*>(w)[t];
        wh2[2 * t + 0] = __floats2half2_rn(fsign(v.x), fsign(v.y));
        wh2[2 * t + 1] = __floats2half2_rn(fsign(v.z), fsign(v.w));
    }
    if (tid < N) g_bs[tid] = fsign(b[tid]);
}

// ---------------- GEMM -------------------------------------------------------
// grid (N/BN=32, M/BM=64), 128 threads (4 warps: 2m x 2n), warp tile 64x64.
// 3-stage cp.async pipeline, stage issue split into 4 quarter-groups.
__global__ void __launch_bounds__(NTHREADS, 2)
gemm_kernel(float* __restrict__ out) {
    extern __shared__ __half smem[];
    const uint32_t sbase = smem_u32(smem);

    const int tid = threadIdx.x;
    const int wid = tid >> 5;
    const int lane = tid & 31;
    const int warp_m = wid & 1;         // 0..1
    const int warp_n = wid >> 1;        // 0..1

    const int bn = blockIdx.x;          // 0..31
    const int bm = blockIdx.y;          // 0..63
    const int bid = bm * gridDim.x + bn;
    const int phase = (bid & 3) * (KT / 4);   // spread L2 k-streams

    // anti-phase: co-resident pairs are ~(b, b+148); offset one of them so
    // the pair's barrier windows interleave instead of colliding.
    if ((bid / 148) & 1)
        asm volatile("nanosleep.u32 256;");

    // per-thread cp.async source pointers
    const int ld_row = tid >> 3;              // 0..15
    const int ld_kc  = tid & 7;               // 0..7 (16B chunk within row)
    const __half* gA_t = g_xh + (size_t)(bm * BM + ld_row) * K + ld_kc * 8;
    const __half* gB_t = g_wh + (size_t)(bn * BN + ld_row) * K + ld_kc * 8;
    const uint32_t s_off = ld_row * ROW_BYTES + ld_kc * 16;

    // ldmatrix per-lane bases
    const int rowA = warp_m * 64 + (lane & 15);
    const int kbA  = (lane >> 4) * 8;                        // halves
    const int rowB = warp_n * 64 + (lane & 7) + (lane >> 4) * 8;
    const int kbB  = ((lane >> 3) & 1) * 8;                  // halves

    float acc[4][8][4];
    #pragma unroll
    for (int i = 0; i < 4; i++)
        #pragma unroll
        for (int j = 0; j < 8; j++)
            #pragma unroll
            for (int e = 0; e < 4; e++) acc[i][j][e] = 0.f;

    // quarter q of stage j: rows [q*32, q*32+32) of both tiles (2+2 cp16),
    // ALWAYS commits a group (empty past the end) to keep accounting uniform.
    auto issue_quarter = [&](int j, int q) {
        if (j < KT) {
            const int kt = (j + phase) & (KT - 1);
            const uint32_t sA = sbase + (j % STAGES) * STAGE_BYTES + s_off;
            const uint32_t sB = sA + TILE_BYTES;
            const __half* gA = gA_t + (size_t)kt * BK;
            const __half* gB = gB_t + (size_t)kt * BK;
            #pragma unroll
            for (int r = 0; r < 2; r++) {
                const int rg = q * 2 + r;    // row-group of 16 rows
                cp16(sA + rg * (16 * ROW_BYTES), gA + (size_t)(rg * 16) * K);
                cp16(sB + rg * (16 * ROW_BYTES), gB + (size_t)(rg * 16) * K);
            }
        }
        cp_commit();
    };

    auto load_frags = [&](int stage, int kk, uint32_t (*a)[4], uint32_t (*b)[4]) {
        const uint32_t sA = sbase + stage * STAGE_BYTES;
        const uint32_t sB = sA + TILE_BYTES;
        #pragma unroll
        for (int im = 0; im < 4; im++)
            ldsm4(a[im], sA + (rowA + im * 16) * ROW_BYTES + (kbA + kk * 16) * 2);
        #pragma unroll
        for (int q = 0; q < 4; q++)
            ldsm4(b[q], sB + (rowB + q * 16) * ROW_BYTES + (kbB + kk * 16) * 2);
    };

    auto mma_half = [&](uint32_t (*a)[4], uint32_t (*b)[4]) {
        #pragma unroll
        for (int im = 0; im < 4; im++)
            #pragma unroll
            for (int jn = 0; jn < 8; jn++)
                mma16816(acc[im][jn],
                         a[im], b[jn >> 1][(jn & 1) * 2],
                                b[jn >> 1][(jn & 1) * 2 + 1]);
    };

    uint32_t a0[4][4], b0[4][4], a1[4][4], b1[4][4];

    // prologue: stages 0,1 issued as 4 quarters each (8 groups);
    // cp_wait<4> leaves <=4 pending (stage 1's quarters) => stage 0 resident.
    #pragma unroll
    for (int q = 0; q < 4; q++) issue_quarter(0, q);
    #pragma unroll
    for (int q = 0; q < 4; q++) issue_quarter(1, q);
    cp_wait<4>();
    __syncthreads();
    load_frags(0, 0, a0, b0);

    for (int j = 0; j < KT; j++) {
        const int st  = j % STAGES;
        const int stn = (j + 1 < KT ? j + 1 : j) % STAGES;

        // stage j+2 spread across the four kk-halves (buffer (j-1)%3 was
        // fully consumed before the barrier at the end of iteration j-1).
        load_frags(st, 1, a1, b1);
        issue_quarter(j + 2, 0);
        mma_half(a0, b0);                   // kk=0

        load_frags(st, 2, a0, b0);
        issue_quarter(j + 2, 1);
        mma_half(a1, b1);                   // kk=1

        load_frags(st, 3, a1, b1);
        issue_quarter(j + 2, 2);
        mma_half(a0, b0);                   // kk=2

        issue_quarter(j + 2, 3);
        // pending = 4 quarters of stage j+2 => everything older (stage j+1)
        // is resident; barrier makes it visible + licenses buffer reuse.
        cp_wait<4>();
        __syncthreads();

        load_frags(stn, 0, a0, b0);         // next iteration, kk=0
        mma_half(a1, b1);                   // kk=3
    }

    // ---------------- epilogue: add sign(bias), store fp32 ------------------
    const int col0 = bn * BN + warp_n * 64 + 2 * (lane & 3);
    const int row0 = bm * BM + warp_m * 64 + (lane >> 2);
    #pragma unroll
    for (int jn = 0; jn < 8; jn++) {
        const int c = col0 + jn * 8;
        const float b0v = g_bs[c];
        const float b1v = g_bs[c + 1];
        #pragma unroll
        for (int im = 0; im < 4; im++) {
            const int r = row0 + im * 16;
            float2 v0 = make_float2(acc[im][jn][0] + b0v, acc[im][jn][1] + b1v);
            float2 v1 = make_float2(acc[im][jn][2] + b0v, acc[im][jn][3] + b1v);
            *reinterpret_cast<float2*>(out + (size_t)r * N + c) = v0;
            *reinterpret_cast<float2*>(out + (size_t)(r + 8) * N + c) = v1;
        }
    }
}

// ---------------- host launch ------------------------------------------------
extern "C" void kernel_launch(void* const* d_in, const int* in_sizes, int n_in,
                              void* d_out, int out_size) {
    const float* x = (const float*)d_in[0];
    const float* w = (const float*)d_in[1];
    const float* b = (const float*)d_in[2];
    float* out = (float*)d_out;

    cudaFuncSetAttribute(gemm_kernel, cudaFuncAttributeMaxDynamicSharedMemorySize,
                         SMEM_TOTAL);

    prep_kernel<<<1024, 256>>>(x, w, b);

    dim3 grid(N / BN, M / BM);   // (32, 64)
    gemm_kernel<<<grid, NTHREADS, SMEM_TOTAL>>>(out);
}

// round 12
// speedup vs baseline: 1.1522x; 1.0392x over previous
#include <cuda_runtime.h>
#include <cuda_fp16.h>
#include <cstdint>

// ============================================================
// out[8192,4096] = x[8192,4096] @ sign(W)[4096,4096]^T + sign(b)
// Base-PTX tensor path: cp.async + ldmatrix + mma.sync.m16n8k16.f32.f16.
// R12: R11 (LDGSTS 4-way spread + anti-phase nanosleep, BK=64, 3 stages,
//      2 CTA/SM) with stage address math HOISTED out of the quarter
//      issues (R11's alu rose to 12.2% from per-quarter recompute).
// ============================================================

static constexpr int M = 8192;
static constexpr int N = 4096;
static constexpr int K = 4096;

static constexpr int BM = 128;
static constexpr int BN = 128;
static constexpr int BK = 64;
static constexpr int KT = K / BK;          // 64 k-tiles
static constexpr int STAGES = 3;
static constexpr int NTHREADS = 128;

static constexpr int ROW_HALFS = BK + 8;   // 72 halves = 144B row (9x16B, conflict-free)
static constexpr int ROW_BYTES = ROW_HALFS * 2;              // 144
static constexpr int TILE_BYTES = BM * ROW_BYTES;            // 18432
static constexpr int STAGE_BYTES = 2 * TILE_BYTES;           // 36864 (A then B)
static constexpr int SMEM_TOTAL = STAGES * STAGE_BYTES;      // 110592

// ---------------- scratch (__device__ globals: alloc-free rule) ------------
__device__ __half g_xh[(size_t)M * K];   // fp16(x)
__device__ __half g_wh[(size_t)N * K];   // fp16(sign(W))
__device__ float  g_bs[N];               // sign(bias)

// ---------------- PTX helpers -----------------------------------------------
__device__ __forceinline__ uint32_t smem_u32(const void* p) {
    uint32_t a;
    asm("{ .reg .u64 t; cvta.to.shared.u64 t, %1; cvt.u32.u64 %0, t; }"
        : "=r"(a) : "l"(p));
    return a;
}

__device__ __forceinline__ void cp16(uint32_t s, const void* g) {
    asm volatile("cp.async.cg.shared.global [%0], [%1], 16;"
                 :: "r"(s), "l"(g) : "memory");
}
__device__ __forceinline__ void cp_commit() {
    asm volatile("cp.async.commit_group;" ::: "memory");
}
template <int NN>
__device__ __forceinline__ void cp_wait() {
    asm volatile("cp.async.wait_group %0;" :: "n"(NN) : "memory");
}

__device__ __forceinline__ void ldsm4(uint32_t* r, uint32_t addr) {
    asm volatile("ldmatrix.sync.aligned.m8n8.x4.shared.b16 {%0,%1,%2,%3}, [%4];"
                 : "=r"(r[0]), "=r"(r[1]), "=r"(r[2]), "=r"(r[3]) : "r"(addr));
}

__device__ __forceinline__ void mma16816(float* c, const uint32_t* a,
                                         uint32_t b0, uint32_t b1) {
    asm volatile(
        "mma.sync.aligned.m16n8k16.row.col.f32.f16.f16.f32 "
        "{%0,%1,%2,%3}, {%4,%5,%6,%7}, {%8,%9}, {%0,%1,%2,%3};"
        : "+f"(c[0]), "+f"(c[1]), "+f"(c[2]), "+f"(c[3])
        : "r"(a[0]), "r"(a[1]), "r"(a[2]), "r"(a[3]), "r"(b0), "r"(b1));
}

// ---------------- prep: fp32 -> fp16 / sign ---------------------------------
__device__ __forceinline__ float fsign(float v) {
    return (v > 0.f) ? 1.f : ((v < 0.f) ? -1.f : 0.f);
}

__global__ void prep_kernel(const float* __restrict__ x,
                            const float* __restrict__ w,
                            const float* __restrict__ b) {
    const long tid = (long)blockIdx.x * blockDim.x + threadIdx.x;
    const long stride = (long)gridDim.x * blockDim.x;
    const long NX4 = ((long)M * K) / 4;
    const long NW4 = ((long)N * K) / 4;

    __half2* xh2 = reinterpret_cast<__half2*>(g_xh);
    __half2* wh2 = reinterpret_cast<__half2*>(g_wh);

    for (long t = tid; t < NX4; t += stride) {
        float4 v = reinterpret_cast<const float4*>(x)[t];
        xh2[2 * t + 0] = __floats2half2_rn(v.x, v.y);
        xh2[2 * t + 1] = __floats2half2_rn(v.z, v.w);
    }
    for (long t = tid; t < NW4; t += stride) {
        float4 v = reinterpret_cast<const float4*>(w)[t];
        wh2[2 * t + 0] = __floats2half2_rn(fsign(v.x), fsign(v.y));
        wh2[2 * t + 1] = __floats2half2_rn(fsign(v.z), fsign(v.w));
    }
    if (tid < N) g_bs[tid] = fsign(b[tid]);
}

// ---------------- GEMM -------------------------------------------------------
// grid (N/BN=32, M/BM=64), 128 threads (4 warps: 2m x 2n), warp tile 64x64.
// 3-stage cp.async pipeline, stage issue split into 4 quarter-groups with
// hoisted address math.
__global__ void __launch_bounds__(NTHREADS, 2)
gemm_kernel(float* __restrict__ out) {
    extern __shared__ __half smem[];
    const uint32_t sbase = smem_u32(smem);

    const int tid = threadIdx.x;
    const int wid = tid >> 5;
    const int lane = tid & 31;
    const int warp_m = wid & 1;         // 0..1
    const int warp_n = wid >> 1;        // 0..1

    const int bn = blockIdx.x;          // 0..31
    const int bm = blockIdx.y;          // 0..63
    const int bid = bm * gridDim.x + bn;
    const int phase = (bid & 3) * (KT / 4);   // spread L2 k-streams

    // anti-phase: co-resident pairs are ~(b, b+148); offset one of them so
    // the pair's barrier windows interleave instead of colliding.
    if ((bid / 148) & 1)
        asm volatile("nanosleep.u32 256;");

    // per-thread cp.async source pointers
    const int ld_row = tid >> 3;              // 0..15
    const int ld_kc  = tid & 7;               // 0..7 (16B chunk within row)
    const __half* gA_t = g_xh + (size_t)(bm * BM + ld_row) * K + ld_kc * 8;
    const __half* gB_t = g_wh + (size_t)(bn * BN + ld_row) * K + ld_kc * 8;
    const uint32_t s_off = ld_row * ROW_BYTES + ld_kc * 16;

    // ldmatrix per-lane bases
    const int rowA = warp_m * 64 + (lane & 15);
    const int kbA  = (lane >> 4) * 8;                        // halves
    const int rowB = warp_n * 64 + (lane & 7) + (lane >> 4) * 8;
    const int kbB  = ((lane >> 3) & 1) * 8;                  // halves

    float acc[4][8][4];
    #pragma unroll
    for (int i = 0; i < 4; i++)
        #pragma unroll
        for (int j = 0; j < 8; j++)
            #pragma unroll
            for (int e = 0; e < 4; e++) acc[i][j][e] = 0.f;

    auto load_frags = [&](int stage, int kk, uint32_t (*a)[4], uint32_t (*b)[4]) {
        const uint32_t sA = sbase + stage * STAGE_BYTES;
        const uint32_t sB = sA + TILE_BYTES;
        #pragma unroll
        for (int im = 0; im < 4; im++)
            ldsm4(a[im], sA + (rowA + im * 16) * ROW_BYTES + (kbA + kk * 16) * 2);
        #pragma unroll
        for (int q = 0; q < 4; q++)
            ldsm4(b[q], sB + (rowB + q * 16) * ROW_BYTES + (kbB + kk * 16) * 2);
    };

    auto mma_half = [&](uint32_t (*a)[4], uint32_t (*b)[4]) {
        #pragma unroll
        for (int im = 0; im < 4; im++)
            #pragma unroll
            for (int jn = 0; jn < 8; jn++)
                mma16816(acc[im][jn],
                         a[im], b[jn >> 1][(jn & 1) * 2],
                                b[jn >> 1][(jn & 1) * 2 + 1]);
    };

    // full-stage issue (prologue only): 4 groups of 4 cp16
    auto issue_full = [&](int j) {
        const int kt = (j + phase) & (KT - 1);
        const uint32_t sA = sbase + (j % STAGES) * STAGE_BYTES + s_off;
        const uint32_t sB = sA + TILE_BYTES;
        const __half* gA = gA_t + (size_t)kt * BK;
        const __half* gB = gB_t + (size_t)kt * BK;
        #pragma unroll
        for (int q = 0; q < 4; q++) {
            #pragma unroll
            for (int r = 0; r < 2; r++) {
                const int rg = q * 2 + r;
                cp16(sA + rg * (16 * ROW_BYTES), gA + (size_t)(rg * 16) * K);
                cp16(sB + rg * (16 * ROW_BYTES), gB + (size_t)(rg * 16) * K);
            }
            cp_commit();
        }
    };

    uint32_t a0[4][4], b0[4][4], a1[4][4], b1[4][4];

    // prologue: stages 0,1 issued as 4 quarters each (8 groups);
    // cp_wait<4> leaves <=4 pending (stage 1's quarters) => stage 0 resident.
    issue_full(0);
    issue_full(1);
    cp_wait<4>();
    __syncthreads();
    load_frags(0, 0, a0, b0);

    for (int j = 0; j < KT; j++) {
        const int st  = j % STAGES;
        const int stn = (j + 1 < KT ? j + 1 : j) % STAGES;

        // ---- hoisted stage-(j+2) addresses (computed once per iteration) ----
        const bool pf = (j + 2 < KT);
        const int kt2 = ((j + 2 + phase) & (KT - 1));
        const uint32_t sA2 = sbase + ((j + 2) % STAGES) * STAGE_BYTES + s_off;
        const uint32_t sB2 = sA2 + TILE_BYTES;
        const __half* gA2 = gA_t + (size_t)kt2 * BK;
        const __half* gB2 = gB_t + (size_t)kt2 * BK;

        // quarter q: rows [q*32, q*32+32) of A and B (constant offsets).
        // Always commits to keep group accounting uniform.
        #define ISSUE_Q(q)                                                    \
            do {                                                              \
                if (pf) {                                                     \
                    cp16(sA2 + (2*(q)+0) * (16 * ROW_BYTES),                  \
                         gA2 + (size_t)((2*(q)+0) * 16) * K);                 \
                    cp16(sB2 + (2*(q)+0) * (16 * ROW_BYTES),                  \
                         gB2 + (size_t)((2*(q)+0) * 16) * K);                 \
                    cp16(sA2 + (2*(q)+1) * (16 * ROW_BYTES),                  \
                         gA2 + (size_t)((2*(q)+1) * 16) * K);                 \
                    cp16(sB2 + (2*(q)+1) * (16 * ROW_BYTES),                  \
                         gB2 + (size_t)((2*(q)+1) * 16) * K);                 \
                }                                                             \
                cp_commit();                                                  \
            } while (0)

        load_frags(st, 1, a1, b1);
        ISSUE_Q(0);
        mma_half(a0, b0);                   // kk=0

        load_frags(st, 2, a0, b0);
        ISSUE_Q(1);
        mma_half(a1, b1);                   // kk=1

        load_frags(st, 3, a1, b1);
        ISSUE_Q(2);
        mma_half(a0, b0);                   // kk=2

        ISSUE_Q(3);
        #undef ISSUE_Q
        // pending = 4 quarters of stage j+2 => stage j+1 resident;
        // barrier makes it visible + licenses buffer reuse.
        cp_wait<4>();
        __syncthreads();

        load_frags(stn, 0, a0, b0);         // next iteration, kk=0
        mma_half(a1, b1);                   // kk=3
    }

    // ---------------- epilogue: add sign(bias), store fp32 ------------------
    const int col0 = bn * BN + warp_n * 64 + 2 * (lane & 3);
    const int row0 = bm * BM + warp_m * 64 + (lane >> 2);
    #pragma unroll
    for (int jn = 0; jn < 8; jn++) {
        const int c = col0 + jn * 8;
        const float b0v = g_bs[c];
        const float b1v = g_bs[c + 1];
        #pragma unroll
        for (int im = 0; im < 4; im++) {
            const int r = row0 + im * 16;
            float2 v0 = make_float2(acc[im][jn][0] + b0v, acc[im][jn][1] + b1v);
            float2 v1 = make_float2(acc[im][jn][2] + b0v, acc[im][jn][3] + b1v);
            *reinterpret_cast<float2*>(out + (size_t)r * N + c) = v0;
            *reinterpret_cast<float2*>(out + (size_t)(r + 8) * N + c) = v1;
        }
    }
}

// ---------------- host launch ------------------------------------------------
extern "C" void kernel_launch(void* const* d_in, const int* in_sizes, int n_in,
                              void* d_out, int out_size) {
    const float* x = (const float*)d_in[0];
    const float* w = (const float*)d_in[1];
    const float* b = (const float*)d_in[2];
    float* out = (float*)d_out;

    cudaFuncSetAttribute(gemm_kernel, cudaFuncAttributeMaxDynamicSharedMemorySize,
                         SMEM_TOTAL);

    prep_kernel<<<1024, 256>>>(x, w, b);

    dim3 grid(N / BN, M / BM);   // (32, 64)
    gemm_kernel<<<grid, NTHREADS, SMEM_TOTAL>>>(out);
}